// round 8
// baseline (speedup 1.0000x reference)
#include <cuda_runtime.h>
#include <cstdint>

#define S_LEN 16384
#define D_DIM 256
#define V_DIM 8
#define K_HEADS 24

typedef unsigned long long u64;

__device__ __forceinline__ u64 packf2(float lo, float hi) {
    u64 r; asm("mov.b64 %0, {%1, %2};" : "=l"(r) : "f"(lo), "f"(hi)); return r;
}
__device__ __forceinline__ void unpackf2(u64 p, float& lo, float& hi) {
    asm("mov.b64 {%0, %1}, %2;" : "=f"(lo), "=f"(hi) : "l"(p));
}
// d += a*b packed f32x2 (2x fp32 FMA throughput on sm_100+)
__device__ __forceinline__ void fmaf2(u64& d, u64 a, u64 b) {
    asm("fma.rn.f32x2 %0, %1, %2, %0;" : "+l"(d) : "l"(a), "l"(b));
}
__device__ __forceinline__ u64 addf2(u64 a, u64 b) {
    u64 r; asm("add.rn.f32x2 %0, %1, %2;" : "=l"(r) : "l"(a), "l"(b)); return r;
}
__device__ __forceinline__ u64 shfl_xor64(u64 v, int m) {
    float lo, hi; unpackf2(v, lo, hi);
    lo = __shfl_xor_sync(0xffffffffu, lo, m);
    hi = __shfl_xor_sync(0xffffffffu, hi, m);
    return packf2(lo, hi);
}

__global__ __launch_bounds__(256, 2)
void attr_decoder_kernel(const float* __restrict__ feats,      // [N, 256]
                         const int*   __restrict__ mask_idx,   // [24, 16384]
                         const float* __restrict__ Wh,         // [24, 256, 8]
                         const float* __restrict__ bias,       // [24, 8]
                         float*       __restrict__ out)        // [24, 16384, 8]
{
    const int k    = blockIdx.y;
    const int lane = threadIdx.x & 31;
    const int warp = threadIdx.x >> 5;
    const int s0   = blockIdx.x * 256 + warp * 32;   // 32 rows per warp

    const int b4 = (lane >> 4) & 1;
    const int b3 = (lane >> 3) & 1;
    const int b2 = (lane >> 2) & 1;
    const int perm = 2 * b4 + b3;                    // v-pair permutation
    const int vown = 4 * b4 + 2 * b3 + b2;           // v this lane finally owns

    // ---- Per-head weights in registers, PRE-PERMUTED -> select-free fold.
    // COALESCED d-map: lane owns d in {4*lane+j} U {128+4*lane+j}, j=0..3.
    // Slot s holds v-pair q = s ^ perm; intra-pair (lo,hi) swapped when b2=1.
    u64 wp[8][4];
    const float4* wk = (const float4*)(Wh + (size_t)k * (D_DIM * V_DIM));
    #pragma unroll
    for (int i = 0; i < 8; ++i) {
        int d = (i < 4) ? (4 * lane + i) : (128 + 4 * lane + (i - 4));
        float4 A = wk[d * 2 + 0];
        float4 B = wk[d * 2 + 1];
        float pv[4][2] = {{A.x, A.y}, {A.z, A.w}, {B.x, B.y}, {B.z, B.w}};
        #pragma unroll
        for (int s = 0; s < 4; ++s) {
            int q = s ^ perm;
            wp[i][s] = packf2(pv[q][b2], pv[q][1 - b2]);
        }
    }
    const float bias_v = bias[k * V_DIM + vown];

    // One gather index per lane covers the warp's 32 rows.
    const int idxv = mask_idx[(size_t)k * S_LEN + s0 + lane];

    // Dense half-row loads: lane reads float4 #lane of each 512B half.
    auto rowptr = [&](int r) -> const float4* {
        int i = __shfl_sync(0xffffffffu, idxv, r);
        return (const float4*)(feats + (size_t)i * D_DIM);
    };

    // ---- Depth-2 register pipeline: buffers A (even rows), B (odd rows).
    const float4* p0 = rowptr(0);
    float4 Aa = p0[lane], Ab = p0[32 + lane];
    const float4* p1 = rowptr(1);
    float4 Ba = p1[lane], Bb = p1[32 + lane];

    float keepval = 0.0f;

    // Process one row given its two float4s; returns folded result (pre-bias).
    auto dorow = [&](const float4& ca, const float4& cb) -> float {
        const float f[8] = {ca.x, ca.y, ca.z, ca.w, cb.x, cb.y, cb.z, cb.w};
        u64 acc2[4] = {0ull, 0ull, 0ull, 0ull};
        #pragma unroll
        for (int i = 0; i < 8; ++i) {
            u64 fd = packf2(f[i], f[i]);
            #pragma unroll
            for (int s = 0; s < 4; ++s) fmaf2(acc2[s], fd, wp[i][s]);
        }
        // Select-free fold: 9 shfl, no FSELs.
        u64 t0 = addf2(acc2[0], shfl_xor64(acc2[2], 16));
        u64 t1 = addf2(acc2[1], shfl_xor64(acc2[3], 16));
        u64 u2 = addf2(t0, shfl_xor64(t1, 8));
        float lo, hi;
        unpackf2(u2, lo, hi);
        float w = lo + __shfl_xor_sync(0xffffffffu, hi, 4);
        w += __shfl_xor_sync(0xffffffffu, w, 2);
        w += __shfl_xor_sync(0xffffffffu, w, 1);
        return w;
    };

    #pragma unroll 2
    for (int r = 0; r < 32; r += 2) {
        // --- even row r: FMA reads A, then reload A for row r+2 (load leads
        //     its use by ~1.5 iterations), then fold.
        {
            const float fA[8] = {Aa.x, Aa.y, Aa.z, Aa.w, Ab.x, Ab.y, Ab.z, Ab.w};
            u64 acc2[4] = {0ull, 0ull, 0ull, 0ull};
            #pragma unroll
            for (int i = 0; i < 8; ++i) {
                u64 fd = packf2(fA[i], fA[i]);
                #pragma unroll
                for (int s = 0; s < 4; ++s) fmaf2(acc2[s], fd, wp[i][s]);
            }
            if (r + 2 < 32) {
                const float4* np = rowptr(r + 2);
                Aa = np[lane];
                Ab = np[32 + lane];
            }
            u64 t0 = addf2(acc2[0], shfl_xor64(acc2[2], 16));
            u64 t1 = addf2(acc2[1], shfl_xor64(acc2[3], 16));
            u64 u2 = addf2(t0, shfl_xor64(t1, 8));
            float lo, hi;
            unpackf2(u2, lo, hi);
            float w = lo + __shfl_xor_sync(0xffffffffu, hi, 4);
            w += __shfl_xor_sync(0xffffffffu, w, 2);
            w += __shfl_xor_sync(0xffffffffu, w, 1);
            if ((lane & 3) == (r & 3)) keepval = w + bias_v;
        }
        // --- odd row r+1: FMA reads B, reload B for row r+3, fold.
        {
            const float fB[8] = {Ba.x, Ba.y, Ba.z, Ba.w, Bb.x, Bb.y, Bb.z, Bb.w};
            u64 acc2[4] = {0ull, 0ull, 0ull, 0ull};
            #pragma unroll
            for (int i = 0; i < 8; ++i) {
                u64 fd = packf2(fB[i], fB[i]);
                #pragma unroll
                for (int s = 0; s < 4; ++s) fmaf2(acc2[s], fd, wp[i][s]);
            }
            if (r + 3 < 32) {
                const float4* np = rowptr(r + 3);
                Ba = np[lane];
                Bb = np[32 + lane];
            }
            u64 t0 = addf2(acc2[0], shfl_xor64(acc2[2], 16));
            u64 t1 = addf2(acc2[1], shfl_xor64(acc2[3], 16));
            u64 u2 = addf2(t0, shfl_xor64(t1, 8));
            float lo, hi;
            unpackf2(u2, lo, hi);
            float w = lo + __shfl_xor_sync(0xffffffffu, hi, 4);
            w += __shfl_xor_sync(0xffffffffu, w, 2);
            w += __shfl_xor_sync(0xffffffffu, w, 1);
            if ((lane & 3) == ((r + 1) & 3)) keepval = w + bias_v;
        }
        // Every 4 rows: one coalesced, lane-permuted 128B warp store.
        if ((r & 3) == 2) {
            out[((size_t)k * S_LEN + s0 + (r - 2) + (lane & 3)) * V_DIM + vown] = keepval;
        }
    }
}

extern "C" void kernel_launch(void* const* d_in, const int* in_sizes, int n_in,
                              void* d_out, int out_size) {
    // metadata order: block_type_grid (unused), features, mask_idx, head_weights, head_bias
    const float* feats    = (const float*)d_in[1];
    const int*   mask_idx = (const int*)  d_in[2];
    const float* Wh       = (const float*)d_in[3];
    const float* bias     = (const float*)d_in[4];
    float*       out      = (float*)d_out;

    dim3 grid(S_LEN / 256, K_HEADS);   // 64 x 24 blocks, 8 warps each, 32 rows/warp
    attr_decoder_kernel<<<grid, 256>>>(feats, mask_idx, Wh, bias, out);
}

// round 9
// speedup vs baseline: 1.0885x; 1.0885x over previous
#include <cuda_runtime.h>
#include <cstdint>

#define S_LEN 16384
#define D_DIM 256
#define V_DIM 8
#define K_HEADS 24
#define DEPTH 6          // cp.async pipeline depth (rows in flight per warp)

typedef unsigned long long u64;

__device__ __forceinline__ u64 packf2(float lo, float hi) {
    u64 r; asm("mov.b64 %0, {%1, %2};" : "=l"(r) : "f"(lo), "f"(hi)); return r;
}
__device__ __forceinline__ void unpackf2(u64 p, float& lo, float& hi) {
    asm("mov.b64 {%0, %1}, %2;" : "=f"(lo), "=f"(hi) : "l"(p));
}
__device__ __forceinline__ void fmaf2(u64& d, u64 a, u64 b) {
    asm("fma.rn.f32x2 %0, %1, %2, %0;" : "+l"(d) : "l"(a), "l"(b));
}
__device__ __forceinline__ u64 addf2(u64 a, u64 b) {
    u64 r; asm("add.rn.f32x2 %0, %1, %2;" : "=l"(r) : "l"(a), "l"(b)); return r;
}
__device__ __forceinline__ u64 shfl_xor64(u64 v, int m) {
    float lo, hi; unpackf2(v, lo, hi);
    lo = __shfl_xor_sync(0xffffffffu, lo, m);
    hi = __shfl_xor_sync(0xffffffffu, hi, m);
    return packf2(lo, hi);
}

__global__ __launch_bounds__(256, 2)
void attr_decoder_kernel(const float* __restrict__ feats,      // [N, 256]
                         const int*   __restrict__ mask_idx,   // [24, 16384]
                         const float* __restrict__ Wh,         // [24, 256, 8]
                         const float* __restrict__ bias,       // [24, 8]
                         float*       __restrict__ out)        // [24, 16384, 8]
{
    // Per-warp cp.async ring: 8 warps x DEPTH rows x 1KB = 48KB static smem.
    __shared__ __align__(16) float ring[8][DEPTH][D_DIM];

    const int k    = blockIdx.y;
    const int lane = threadIdx.x & 31;
    const int warp = threadIdx.x >> 5;
    const int s0   = blockIdx.x * 256 + warp * 32;   // 32 rows per warp

    // One gather index per lane covers the warp's 32 rows.
    const int idxv = mask_idx[(size_t)k * S_LEN + s0 + lane];

    // Lane copies the exact 32B it will read back: float4 #lane of each 512B half.
    auto issue_row = [&](int r) {
        int i = __shfl_sync(0xffffffffu, idxv, r);
        const float* src = feats + (size_t)i * D_DIM + lane * 4;
        uint32_t dst = (uint32_t)__cvta_generic_to_shared(
            &ring[warp][r % DEPTH][lane * 4]);
        asm volatile("cp.async.cg.shared.global [%0], [%1], 16;"
                     :: "r"(dst), "l"(src));
        asm volatile("cp.async.cg.shared.global [%0], [%1], 16;"
                     :: "r"(dst + 512), "l"(src + 128));
        asm volatile("cp.async.commit_group;" ::: "memory");
    };

    // ---- Prologue: fill the pipeline BEFORE loading weights, so the first
    // rows' DRAM latency overlaps the weight loads.
    #pragma unroll
    for (int p = 0; p < DEPTH; ++p) issue_row(p);

    const int b4 = (lane >> 4) & 1;
    const int b3 = (lane >> 3) & 1;
    const int b2 = (lane >> 2) & 1;
    const int perm = 2 * b4 + b3;
    const int vown = 4 * b4 + 2 * b3 + b2;

    // ---- Weights in registers, pre-permuted -> select-free fold.
    // Coalesced d-map: lane owns d in {4*lane+j} U {128+4*lane+j}, j=0..3.
    u64 wp[8][4];
    const float4* wk = (const float4*)(Wh + (size_t)k * (D_DIM * V_DIM));
    #pragma unroll
    for (int i = 0; i < 8; ++i) {
        int d = (i < 4) ? (4 * lane + i) : (128 + 4 * lane + (i - 4));
        float4 A = wk[d * 2 + 0];
        float4 B = wk[d * 2 + 1];
        float pv[4][2] = {{A.x, A.y}, {A.z, A.w}, {B.x, B.y}, {B.z, B.w}};
        #pragma unroll
        for (int s = 0; s < 4; ++s) {
            int q = s ^ perm;
            wp[i][s] = packf2(pv[q][b2], pv[q][1 - b2]);
        }
    }
    const float bias_v = bias[k * V_DIM + vown];

    float keepval = 0.0f;
    int slot = 0;

    #pragma unroll 2
    for (int r = 0; r < 32; ++r) {
        // Row r's group is the oldest; allow DEPTH-1 newer groups pending.
        asm volatile("cp.async.wait_group %0;" :: "n"(DEPTH - 1) : "memory");

        // Read back own 32B (no cross-lane visibility needed -> no syncwarp).
        const float4* rp = (const float4*)&ring[warp][slot][0];
        const float4 ca = rp[lane];
        const float4 cb = rp[32 + lane];

        // ---- Packed FMA: acc2[s] = partial v-pair over this lane's 8 d's.
        const float f[8] = {ca.x, ca.y, ca.z, ca.w, cb.x, cb.y, cb.z, cb.w};
        u64 acc2[4] = {0ull, 0ull, 0ull, 0ull};
        #pragma unroll
        for (int i = 0; i < 8; ++i) {
            u64 fd = packf2(f[i], f[i]);
            #pragma unroll
            for (int s = 0; s < 4; ++s) fmaf2(acc2[s], fd, wp[i][s]);
        }

        // Refill this slot for row r+DEPTH (FMAs above consumed ca/cb, so the
        // LDS reads are complete). Tail: empty group keeps wait arithmetic exact.
        if (r + DEPTH < 32) {
            issue_row(r + DEPTH);
        } else {
            asm volatile("cp.async.commit_group;" ::: "memory");
        }
        if (++slot == DEPTH) slot = 0;

        // ---- Select-free fold: 9 shfl, no selects (weights pre-permuted).
        u64 t0 = addf2(acc2[0], shfl_xor64(acc2[2], 16));
        u64 t1 = addf2(acc2[1], shfl_xor64(acc2[3], 16));
        u64 u2 = addf2(t0, shfl_xor64(t1, 8));
        float lo, hi;
        unpackf2(u2, lo, hi);
        float w = lo + __shfl_xor_sync(0xffffffffu, hi, 4);
        w += __shfl_xor_sync(0xffffffffu, w, 2);
        w += __shfl_xor_sync(0xffffffffu, w, 1);
        const float res = w + bias_v;   // lane l holds v=vown, replica over l&3

        // Buffer 4 rows, then one coalesced lane-permuted 128B warp store.
        if ((lane & 3) == (r & 3)) keepval = res;
        if ((r & 3) == 3) {
            out[((size_t)k * S_LEN + s0 + (r - 3) + (lane & 3)) * V_DIM + vown] = keepval;
        }
    }
}

extern "C" void kernel_launch(void* const* d_in, const int* in_sizes, int n_in,
                              void* d_out, int out_size) {
    // metadata order: block_type_grid (unused), features, mask_idx, head_weights, head_bias
    const float* feats    = (const float*)d_in[1];
    const int*   mask_idx = (const int*)  d_in[2];
    const float* Wh       = (const float*)d_in[3];
    const float* bias     = (const float*)d_in[4];
    float*       out      = (float*)d_out;

    dim3 grid(S_LEN / 256, K_HEADS);   // 64 x 24 blocks, 8 warps each, 32 rows/warp
    attr_decoder_kernel<<<grid, 256>>>(feats, mask_idx, Wh, bias, out);
}